// round 11
// baseline (speedup 1.0000x reference)
#include <cuda_runtime.h>
#include <cuda_fp16.h>
#include <cstdint>

#define TPB 128
#define RPB 64
#define PAD 136    // fp16 elems per k-row of A2 tile (272B stride, conflict-free)

// ---------------- fragment-ordered split-fp16 weights in device globals ----
// W2: 512 fragments (c8 x ni2 x kt8 x nt4), each 32 lanes x uint4{hi0,hi1,lo0,lo1}
__device__ __align__(16) uint4 gW2f[16384];
// W4: 160 fragments (c8 x ni2 x kt2 x nt5)
__device__ __align__(16) uint4 gW4f[5120];

__device__ __forceinline__ void split_pack(float a, float b, uint32_t& hi, uint32_t& lo) {
    __half ha = __float2half_rn(a), hb = __float2half_rn(b);
    __half la = __float2half_rn(a - __half2float(ha));
    __half lb = __float2half_rn(b - __half2float(hb));
    __half2 ph = __halves2half2(ha, hb), pl = __halves2half2(la, lb);
    hi = *(uint32_t*)&ph;
    lo = *(uint32_t*)&pl;
}

__global__ void prep_kernel(const float* __restrict__ W2,
                            const float* __restrict__ W4) {
    int idx = blockIdx.x * blockDim.x + threadIdx.x;
    if (idx < 16384) {
        int lane = idx & 31, fid = idx >> 5;
        int nt = fid & 3, kt = (fid >> 2) & 7, ni = (fid >> 5) & 1, c = fid >> 6;
        int n  = c * 64 + ni * 32 + nt * 8 + (lane >> 2);
        int k0 = kt * 16 + (lane & 3) * 2;
        uint32_t h0, l0, h1, l1;
        split_pack(W2[k0 * 512 + n],       W2[(k0 + 1) * 512 + n], h0, l0);
        split_pack(W2[(k0 + 8) * 512 + n], W2[(k0 + 9) * 512 + n], h1, l1);
        gW2f[idx] = make_uint4(h0, h1, l0, l1);
    } else if (idx < 16384 + 5120) {
        int i = idx - 16384;
        int lane = i & 31, fid = i >> 5;
        int nt = fid % 5, r = fid / 5;
        int kt = r & 1, ni = (r >> 1) & 1, c = r >> 2;
        int n = nt * 8 + (lane >> 2);
        int k = c * 64 + ni * 32 + kt * 16 + (lane & 3) * 2;
        uint32_t h0, l0, h1, l1;
        split_pack(W4[k * 40 + n],       W4[(k + 1) * 40 + n], h0, l0);
        split_pack(W4[(k + 8) * 40 + n], W4[(k + 9) * 40 + n], h1, l1);
        gW4f[i] = make_uint4(h0, h1, l0, l1);
    }
}

// ---------------- PTX helpers ----------------
__device__ __forceinline__ uint32_t smem_u32(const void* p) {
    uint32_t a;
    asm("{ .reg .u64 t; cvta.to.shared.u64 t, %1; cvt.u32.u64 %0, t; }"
        : "=r"(a) : "l"(p));
    return a;
}
__device__ __forceinline__ void ldsm_x4(uint32_t* r, uint32_t addr) {
    asm volatile("ldmatrix.sync.aligned.m8n8.x4.shared.b16 {%0,%1,%2,%3}, [%4];"
        : "=r"(r[0]), "=r"(r[1]), "=r"(r[2]), "=r"(r[3]) : "r"(addr));
}
__device__ __forceinline__ void mma16816(float* d, const uint32_t* a,
                                         uint32_t b0, uint32_t b1) {
    asm volatile("mma.sync.aligned.m16n8k16.row.col.f32.f16.f16.f32 "
        "{%0,%1,%2,%3}, {%4,%5,%6,%7}, {%8,%9}, {%0,%1,%2,%3};"
        : "+f"(d[0]), "+f"(d[1]), "+f"(d[2]), "+f"(d[3])
        : "r"(a[0]), "r"(a[1]), "r"(a[2]), "r"(a[3]), "r"(b0), "r"(b1));
}
__device__ __forceinline__ uint32_t pack_relu_h2(float v0, float v1, float b0, float b1) {
    __half2 p = __floats2half2_rn(fmaxf(v0 + b0, 0.f), fmaxf(v1 + b1, 0.f));
    return *(uint32_t*)&p;
}

// ---------------- smem layout (bytes) ----------------
#define S_A2H   0          // h1 hi [64][PAD] f16 = 17408 ; later sred 10240
#define S_STAGE 17408      // layer1 staging: xs 3840 + W1p 18432
#define S_BIAS  39680      // b1(128) b2(512) b4(40) f32 = 2720
#define SMEM_BYTES 42400

__global__ __launch_bounds__(TPB, 2)
void dqn_hmma_kernel(const float* __restrict__ x,
                     const float* __restrict__ W1,
                     const float* __restrict__ b1,
                     const float* __restrict__ b2,
                     const float* __restrict__ b4,
                     float* __restrict__ out) {
    extern __shared__ char smem[];
    const uint32_t sb = smem_u32(smem);
    const int t    = threadIdx.x;
    const int wid  = t >> 5;
    const int lane = t & 31;
    const int blk  = blockIdx.x;

    float* b1s = (float*)(smem + S_BIAS);
    float* b2s = b1s + 128;
    float* b4s = b2s + 512;

    // ---------------- stage biases + layer1 inputs ----------------
    {
        float* xs  = (float*)(smem + S_STAGE);
        float* W1p = xs + 960;
        const float* xg = x + (size_t)blk * (RPB * 15);
        #pragma unroll
        for (int i = 0; i < 8; i++) {
            int idx = i * TPB + t;
            if (idx < 960) xs[idx] = xg[idx];
        }
        #pragma unroll
        for (int i = 0; i < 36; i++) W1p[i * TPB + t] = W1[i * TPB + t];
        if (t < 128) b1s[t] = b1[t];
        #pragma unroll
        for (int i = 0; i < 4; i++) b2s[i * TPB + t] = b2[i * TPB + t];
        if (t < 40) b4s[t] = b4[t];
        __syncthreads();

        // ---------------- layer 1 (fp32 exact) -> fp16-hi A2 tile --------
        const int r  = t & 63;
        const int ch = t >> 6;
        const float* xr = xs + r * 15;
        float keep[11];
        #pragma unroll
        for (int k = 0; k < 11; k++) keep[k] = xr[k];
        int hh = (int)xr[11];      hh = hh < 0 ? 0 : (hh > 3 ? 3 : hh);
        int n0 = (int)xr[12] - 1;  n0 = n0 < 0 ? 0 : (n0 > 6 ? 6 : n0);
        int n1 = (int)xr[13] - 1;  n1 = n1 < 0 ? 0 : (n1 > 6 ? 6 : n1);
        int n2 = (int)xr[14] - 1;  n2 = n2 < 0 ? 0 : (n2 > 6 ? 6 : n2);
        const float* hrow = W1p + (11 + hh) * 128;
        const float* g0   = W1p + (15 + n0) * 128;
        const float* g1   = W1p + (22 + n1) * 128;
        const float* g2   = W1p + (29 + n2) * 128;

        #pragma unroll
        for (int c4 = 0; c4 < 16; c4++) {
            const int c = ch * 64 + c4 * 4;
            float4 acc = *(const float4*)(b1s + c);
            #pragma unroll
            for (int k = 0; k < 11; k++) {
                float4 w = *(const float4*)(W1p + k * 128 + c);
                acc.x += keep[k] * w.x; acc.y += keep[k] * w.y;
                acc.z += keep[k] * w.z; acc.w += keep[k] * w.w;
            }
            float4 wh = *(const float4*)(hrow + c);
            float4 w0 = *(const float4*)(g0 + c);
            float4 w1 = *(const float4*)(g1 + c);
            float4 w2 = *(const float4*)(g2 + c);
            __half h0v = __float2half_rn(fmaxf(acc.x + wh.x + w0.x + w1.x + w2.x, 0.f));
            __half h1v = __float2half_rn(fmaxf(acc.y + wh.y + w0.y + w1.y + w2.y, 0.f));
            __half h2v = __float2half_rn(fmaxf(acc.z + wh.z + w0.z + w1.z + w2.z, 0.f));
            __half h3v = __float2half_rn(fmaxf(acc.w + wh.w + w0.w + w1.w + w2.w, 0.f));
            uint32_t off = (uint32_t)(r * PAD + c) * 2u;
            *(__half2*)(smem + S_A2H + off)     = __halves2half2(h0v, h1v);
            *(__half2*)(smem + S_A2H + off + 4) = __halves2half2(h2v, h3v);
        }
    }
    __syncthreads();

    // ---------------- fragment lane mappings ----------------
    const int lr  = lane & 15;
    const int lc  = (lane >> 4) << 3;
    const int gid = lane >> 2;
    const int tig = lane & 3;

    const int mi = wid & 1;                 // M32 block (layers 2+3)
    const int ni = wid >> 1;                // layer2 N32 block == layer3 K32 half

    // ---- preload register-resident A fragments (h1-hi, 32x128 per warp) ----
    uint32_t a2f[2][8][4];
    #pragma unroll
    for (int kt = 0; kt < 8; kt++)
        #pragma unroll
        for (int mt = 0; mt < 2; mt++) {
            uint32_t off = (uint32_t)((mi * 32 + mt * 16 + lr) * PAD + kt * 16 + lc) * 2u;
            ldsm_x4(a2f[mt][kt], sb + S_A2H + off);
        }
    __syncthreads();   // A2 region now reusable as sred

    float o3[2][5][4];
    #pragma unroll
    for (int a = 0; a < 2; a++)
        #pragma unroll
        for (int b = 0; b < 5; b++)
            #pragma unroll
            for (int d = 0; d < 4; d++) o3[a][b][d] = 0.f;

    // ---------------- chunk loop: 8 x 64 j-cols, NO barriers ----------------
    #pragma unroll 1
    for (int c = 0; c < 8; c++) {
        float acc[2][4][4];
        #pragma unroll
        for (int a = 0; a < 2; a++)
            #pragma unroll
            for (int b = 0; b < 4; b++)
                #pragma unroll
                for (int d = 0; d < 4; d++) acc[a][b][d] = 0.f;

        const uint4* w2base = gW2f + ((size_t)(c * 2 + ni) << 10) + lane;
        const uint4* w4base = gW4f + (size_t)((c * 2 + ni) * 2 * 5) * 32 + lane;

        // ---- layer2: double-buffered B fragments, two-pass hi/lo MMA ----
        uint4 w[4], wn[4];
        #pragma unroll
        for (int nt = 0; nt < 4; nt++) w[nt] = __ldg(w2base + nt * 32);

        #pragma unroll
        for (int kt = 0; kt < 8; kt++) {
            // prefetch next kt's fragments before consuming current
            if (kt < 7) {
                #pragma unroll
                for (int nt = 0; nt < 4; nt++)
                    wn[nt] = __ldg(w2base + ((kt + 1) * 4 + nt) * 32);
            }
            // pass 1: hi terms (8 independent accumulators)
            #pragma unroll
            for (int mt = 0; mt < 2; mt++)
                #pragma unroll
                for (int nt = 0; nt < 4; nt++)
                    mma16816(acc[mt][nt], a2f[mt][kt], w[nt].x, w[nt].y);
            // pass 2: lo terms
            #pragma unroll
            for (int mt = 0; mt < 2; mt++)
                #pragma unroll
                for (int nt = 0; nt < 4; nt++)
                    mma16816(acc[mt][nt], a2f[mt][kt], w[nt].z, w[nt].w);
            #pragma unroll
            for (int nt = 0; nt < 4; nt++) w[nt] = wn[nt];
        }

        // ---- prefetch ALL layer3 W4 fragments before epilogue math ----
        uint4 w4[2][5];
        #pragma unroll
        for (int kt = 0; kt < 2; kt++)
            #pragma unroll
            for (int nt = 0; nt < 5; nt++)
                w4[kt][nt] = __ldg(w4base + (kt * 5 + nt) * 32);

        // ---- epilogue in registers: D-frag -> A-frag (h2), +b2, relu, cvt ----
        uint32_t a3f[2][2][4];
        #pragma unroll
        for (int mt = 0; mt < 2; mt++)
            #pragma unroll
            for (int nt = 0; nt < 4; nt++) {
                int j = c * 64 + ni * 32 + nt * 8 + 2 * tig;
                float bj0 = b2s[j], bj1 = b2s[j + 1];
                uint32_t p01 = pack_relu_h2(acc[mt][nt][0], acc[mt][nt][1], bj0, bj1);
                uint32_t p23 = pack_relu_h2(acc[mt][nt][2], acc[mt][nt][3], bj0, bj1);
                a3f[mt][nt >> 1][(nt & 1) * 2]     = p01;
                a3f[mt][nt >> 1][(nt & 1) * 2 + 1] = p23;
            }

        // ---- layer3 partial: two-pass hi/lo ----
        #pragma unroll
        for (int kt = 0; kt < 2; kt++) {
            #pragma unroll
            for (int mt = 0; mt < 2; mt++)
                #pragma unroll
                for (int nt = 0; nt < 5; nt++)
                    mma16816(o3[mt][nt], a3f[mt][kt], w4[kt][nt].x, w4[kt][nt].y);
            #pragma unroll
            for (int mt = 0; mt < 2; mt++)
                #pragma unroll
                for (int nt = 0; nt < 5; nt++)
                    mma16816(o3[mt][nt], a3f[mt][kt], w4[kt][nt].z, w4[kt][nt].w);
        }
    }

    // ---------------- cross-warp K reduction (2-way over ni) + output -------
    float* sred = (float*)smem;   // aliases A2 region: 64*40 f32 = 10240B
    if (ni == 1) {
        #pragma unroll
        for (int mt = 0; mt < 2; mt++)
            #pragma unroll
            for (int nt = 0; nt < 5; nt++) {
                int j = nt * 8 + 2 * tig;
                int r0 = mi * 32 + mt * 16 + gid;
                int r1 = r0 + 8;
                sred[r0 * 40 + j]     = o3[mt][nt][0];
                sred[r0 * 40 + j + 1] = o3[mt][nt][1];
                sred[r1 * 40 + j]     = o3[mt][nt][2];
                sred[r1 * 40 + j + 1] = o3[mt][nt][3];
            }
    }
    __syncthreads();
    if (ni == 0) {
        #pragma unroll
        for (int mt = 0; mt < 2; mt++)
            #pragma unroll
            for (int nt = 0; nt < 5; nt++) {
                int j = nt * 8 + 2 * tig;
                int r0 = mi * 32 + mt * 16 + gid;
                int r1 = r0 + 8;
                float s0 = o3[mt][nt][0] + sred[r0 * 40 + j]     + b4s[j];
                float s1 = o3[mt][nt][1] + sred[r0 * 40 + j + 1] + b4s[j + 1];
                float s2 = o3[mt][nt][2] + sred[r1 * 40 + j]     + b4s[j];
                float s3 = o3[mt][nt][3] + sred[r1 * 40 + j + 1] + b4s[j + 1];
                *(float2*)(out + ((size_t)blk * RPB + r0) * 40 + j) = make_float2(s0, s1);
                *(float2*)(out + ((size_t)blk * RPB + r1) * 40 + j) = make_float2(s2, s3);
            }
    }
}

extern "C" void kernel_launch(void* const* d_in, const int* in_sizes, int n_in,
                              void* d_out, int out_size) {
    const float* x  = (const float*)d_in[0];
    const float* W1 = (const float*)d_in[1];
    const float* b1 = (const float*)d_in[2];
    const float* W2 = (const float*)d_in[3];
    const float* b2 = (const float*)d_in[4];
    const float* W4 = (const float*)d_in[5];
    const float* b4 = (const float*)d_in[6];
    float* out = (float*)d_out;

    prep_kernel<<<84, 256>>>(W2, W4);

    const int B = in_sizes[0] / 15;      // 131072
    const int grid = B / RPB;            // 2048
    cudaFuncSetAttribute(dqn_hmma_kernel,
                         cudaFuncAttributeMaxDynamicSharedMemorySize, SMEM_BYTES);
    dqn_hmma_kernel<<<grid, TPB, SMEM_BYTES>>>(x, W1, b1, b2, b4, out);
}

// round 12
// speedup vs baseline: 1.4634x; 1.4634x over previous
#include <cuda_runtime.h>
#include <cuda_fp16.h>
#include <cstdint>

#define TPB 128
#define RPB 64
#define PAD 136    // fp16 elems per k-row of A2 tile (272B stride, conflict-free)

// ---------------- fragment-ordered fp16 weights in device globals ----------
// W2: entries (c8 x ni2 x kt8 x ntp2) x 32 lanes; uint4 = {ntA.b0, ntA.b1, ntB.b0, ntB.b1}
__device__ __align__(16) uint4 gW2f[8192];
// W4: entries (c8 x ni2 x nt5) x 32 lanes; uint4 = {kt0.b0, kt0.b1, kt1.b0, kt1.b1}
__device__ __align__(16) uint4 gW4f[2560];

__device__ __forceinline__ uint32_t pack_h2(float a, float b) {
    __half2 p = __floats2half2_rn(a, b);
    return *(uint32_t*)&p;
}

__global__ void prep_kernel(const float* __restrict__ W2,
                            const float* __restrict__ W4) {
    int idx = blockIdx.x * blockDim.x + threadIdx.x;
    if (idx < 8192) {
        // fid = ((c*2+ni)*8+kt)*2+ntp
        int lane = idx & 31, fid = idx >> 5;
        int ntp = fid & 1, kt = (fid >> 1) & 7, ni = (fid >> 4) & 1, c = fid >> 5;
        int nA = c * 64 + ni * 32 + (2 * ntp) * 8 + (lane >> 2);
        int nB = nA + 8;
        int k0 = kt * 16 + (lane & 3) * 2;
        uint4 v;
        v.x = pack_h2(W2[k0 * 512 + nA],       W2[(k0 + 1) * 512 + nA]);
        v.y = pack_h2(W2[(k0 + 8) * 512 + nA], W2[(k0 + 9) * 512 + nA]);
        v.z = pack_h2(W2[k0 * 512 + nB],       W2[(k0 + 1) * 512 + nB]);
        v.w = pack_h2(W2[(k0 + 8) * 512 + nB], W2[(k0 + 9) * 512 + nB]);
        gW2f[idx] = v;
    } else if (idx < 8192 + 2560) {
        // fid = (c*2+ni)*5 + nt
        int i = idx - 8192;
        int lane = i & 31, fid = i >> 5;
        int nt = fid % 5, r = fid / 5;
        int ni = r & 1, c = r >> 1;
        int n = nt * 8 + (lane >> 2);
        int k0 = c * 64 + ni * 32 + (lane & 3) * 2;   // kt=0
        int k1 = k0 + 16;                             // kt=1
        uint4 v;
        v.x = pack_h2(W4[k0 * 40 + n],       W4[(k0 + 1) * 40 + n]);
        v.y = pack_h2(W4[(k0 + 8) * 40 + n], W4[(k0 + 9) * 40 + n]);
        v.z = pack_h2(W4[k1 * 40 + n],       W4[(k1 + 1) * 40 + n]);
        v.w = pack_h2(W4[(k1 + 8) * 40 + n], W4[(k1 + 9) * 40 + n]);
        gW4f[i] = v;
    }
}

// ---------------- PTX helpers ----------------
__device__ __forceinline__ uint32_t smem_u32(const void* p) {
    uint32_t a;
    asm("{ .reg .u64 t; cvta.to.shared.u64 t, %1; cvt.u32.u64 %0, t; }"
        : "=r"(a) : "l"(p));
    return a;
}
__device__ __forceinline__ void ldsm_x4(uint32_t* r, uint32_t addr) {
    asm volatile("ldmatrix.sync.aligned.m8n8.x4.shared.b16 {%0,%1,%2,%3}, [%4];"
        : "=r"(r[0]), "=r"(r[1]), "=r"(r[2]), "=r"(r[3]) : "r"(addr));
}
__device__ __forceinline__ void mma16816(float* d, const uint32_t* a,
                                         uint32_t b0, uint32_t b1) {
    asm volatile("mma.sync.aligned.m16n8k16.row.col.f32.f16.f16.f32 "
        "{%0,%1,%2,%3}, {%4,%5,%6,%7}, {%8,%9}, {%0,%1,%2,%3};"
        : "+f"(d[0]), "+f"(d[1]), "+f"(d[2]), "+f"(d[3])
        : "r"(a[0]), "r"(a[1]), "r"(a[2]), "r"(a[3]), "r"(b0), "r"(b1));
}
__device__ __forceinline__ uint32_t pack_relu_h2(float v0, float v1, float b0, float b1) {
    __half2 p = __floats2half2_rn(fmaxf(v0 + b0, 0.f), fmaxf(v1 + b1, 0.f));
    return *(uint32_t*)&p;
}

// ---------------- smem layout (bytes) ----------------
#define S_A2H   0          // h1 hi [64][PAD] f16 = 17408 ; later sred 10240
#define S_STAGE 17408      // layer1 staging: xs 3840 + W1p 18432
#define S_BIAS  39680      // b1(128) b2(512) b4(40) f32 = 2720
#define SMEM_BYTES 42400

__global__ __launch_bounds__(TPB, 3)
void dqn_hmma_kernel(const float* __restrict__ x,
                     const float* __restrict__ W1,
                     const float* __restrict__ b1,
                     const float* __restrict__ b2,
                     const float* __restrict__ b4,
                     float* __restrict__ out) {
    extern __shared__ char smem[];
    const uint32_t sb = smem_u32(smem);
    const int t    = threadIdx.x;
    const int wid  = t >> 5;
    const int lane = t & 31;
    const int blk  = blockIdx.x;

    float* b1s = (float*)(smem + S_BIAS);
    float* b2s = b1s + 128;
    float* b4s = b2s + 512;

    // ---------------- stage biases + layer1 inputs ----------------
    {
        float* xs  = (float*)(smem + S_STAGE);
        float* W1p = xs + 960;
        const float* xg = x + (size_t)blk * (RPB * 15);
        #pragma unroll
        for (int i = 0; i < 8; i++) {
            int idx = i * TPB + t;
            if (idx < 960) xs[idx] = xg[idx];
        }
        #pragma unroll
        for (int i = 0; i < 36; i++) W1p[i * TPB + t] = W1[i * TPB + t];
        if (t < 128) b1s[t] = b1[t];
        #pragma unroll
        for (int i = 0; i < 4; i++) b2s[i * TPB + t] = b2[i * TPB + t];
        if (t < 40) b4s[t] = b4[t];
        __syncthreads();

        // ---------------- layer 1 (fp32 exact) -> fp16-hi A2 tile --------
        const int r  = t & 63;
        const int ch = t >> 6;
        const float* xr = xs + r * 15;
        float keep[11];
        #pragma unroll
        for (int k = 0; k < 11; k++) keep[k] = xr[k];
        int hh = (int)xr[11];      hh = hh < 0 ? 0 : (hh > 3 ? 3 : hh);
        int n0 = (int)xr[12] - 1;  n0 = n0 < 0 ? 0 : (n0 > 6 ? 6 : n0);
        int n1 = (int)xr[13] - 1;  n1 = n1 < 0 ? 0 : (n1 > 6 ? 6 : n1);
        int n2 = (int)xr[14] - 1;  n2 = n2 < 0 ? 0 : (n2 > 6 ? 6 : n2);
        const float* hrow = W1p + (11 + hh) * 128;
        const float* g0   = W1p + (15 + n0) * 128;
        const float* g1   = W1p + (22 + n1) * 128;
        const float* g2   = W1p + (29 + n2) * 128;

        #pragma unroll
        for (int c4 = 0; c4 < 16; c4++) {
            const int c = ch * 64 + c4 * 4;
            float4 acc = *(const float4*)(b1s + c);
            #pragma unroll
            for (int k = 0; k < 11; k++) {
                float4 w = *(const float4*)(W1p + k * 128 + c);
                acc.x += keep[k] * w.x; acc.y += keep[k] * w.y;
                acc.z += keep[k] * w.z; acc.w += keep[k] * w.w;
            }
            float4 wh = *(const float4*)(hrow + c);
            float4 w0 = *(const float4*)(g0 + c);
            float4 w1 = *(const float4*)(g1 + c);
            float4 w2 = *(const float4*)(g2 + c);
            __half h0v = __float2half_rn(fmaxf(acc.x + wh.x + w0.x + w1.x + w2.x, 0.f));
            __half h1v = __float2half_rn(fmaxf(acc.y + wh.y + w0.y + w1.y + w2.y, 0.f));
            __half h2v = __float2half_rn(fmaxf(acc.z + wh.z + w0.z + w1.z + w2.z, 0.f));
            __half h3v = __float2half_rn(fmaxf(acc.w + wh.w + w0.w + w1.w + w2.w, 0.f));
            uint32_t off = (uint32_t)(r * PAD + c) * 2u;
            *(__half2*)(smem + S_A2H + off)     = __halves2half2(h0v, h1v);
            *(__half2*)(smem + S_A2H + off + 4) = __halves2half2(h2v, h3v);
        }
    }
    __syncthreads();

    // ---------------- fragment lane mappings ----------------
    const int lr  = lane & 15;
    const int lc  = (lane >> 4) << 3;
    const int gid = lane >> 2;
    const int tig = lane & 3;

    const int mi = wid & 1;                 // M32 block (layers 2+3)
    const int ni = wid >> 1;                // layer2 N32 block == layer3 K32 half

    // ---- preload register-resident A fragments (h1-hi, 32x128 per warp) ----
    uint32_t a2f[2][8][4];
    #pragma unroll
    for (int kt = 0; kt < 8; kt++)
        #pragma unroll
        for (int mt = 0; mt < 2; mt++) {
            uint32_t off = (uint32_t)((mi * 32 + mt * 16 + lr) * PAD + kt * 16 + lc) * 2u;
            ldsm_x4(a2f[mt][kt], sb + S_A2H + off);
        }
    __syncthreads();   // A2 region now reusable as sred

    float o3[2][5][4];
    #pragma unroll
    for (int a = 0; a < 2; a++)
        #pragma unroll
        for (int b = 0; b < 5; b++)
            #pragma unroll
            for (int d = 0; d < 4; d++) o3[a][b][d] = 0.f;

    // ---------------- chunk loop: 8 x 64 j-cols, NO barriers ----------------
    #pragma unroll 1
    for (int c = 0; c < 8; c++) {
        float acc[2][4][4];
        #pragma unroll
        for (int a = 0; a < 2; a++)
            #pragma unroll
            for (int b = 0; b < 4; b++)
                #pragma unroll
                for (int d = 0; d < 4; d++) acc[a][b][d] = 0.f;

        const uint4* w2base = gW2f + ((size_t)(c * 2 + ni) << 9) + lane;   // 16 entries * 32
        const uint4* w4base = gW4f + (size_t)((c * 2 + ni) * 5) * 32 + lane;

        // ---- layer2: fp16 B fragments direct from gmem (2 LDG.128 per kt) ----
        #pragma unroll
        for (int kt = 0; kt < 8; kt++) {
            uint4 wA = __ldg(w2base + (kt * 2 + 0) * 32);   // n-tiles 0,1
            uint4 wB = __ldg(w2base + (kt * 2 + 1) * 32);   // n-tiles 2,3
            #pragma unroll
            for (int mt = 0; mt < 2; mt++) {
                mma16816(acc[mt][0], a2f[mt][kt], wA.x, wA.y);
                mma16816(acc[mt][1], a2f[mt][kt], wA.z, wA.w);
                mma16816(acc[mt][2], a2f[mt][kt], wB.x, wB.y);
                mma16816(acc[mt][3], a2f[mt][kt], wB.z, wB.w);
            }
        }

        // ---- prefetch layer3 W4 fragments (5 LDG.128) ----
        uint4 w4[5];
        #pragma unroll
        for (int nt = 0; nt < 5; nt++) w4[nt] = __ldg(w4base + nt * 32);

        // ---- epilogue in registers: D-frag -> A-frag (h2), +b2, relu, cvt ----
        uint32_t a3f[2][2][4];
        #pragma unroll
        for (int mt = 0; mt < 2; mt++)
            #pragma unroll
            for (int nt = 0; nt < 4; nt++) {
                int j = c * 64 + ni * 32 + nt * 8 + 2 * tig;
                float bj0 = b2s[j], bj1 = b2s[j + 1];
                uint32_t p01 = pack_relu_h2(acc[mt][nt][0], acc[mt][nt][1], bj0, bj1);
                uint32_t p23 = pack_relu_h2(acc[mt][nt][2], acc[mt][nt][3], bj0, bj1);
                a3f[mt][nt >> 1][(nt & 1) * 2]     = p01;
                a3f[mt][nt >> 1][(nt & 1) * 2 + 1] = p23;
            }

        // ---- layer3 partial: K = this warp's j-window (ni half), from regs ----
        #pragma unroll
        for (int mt = 0; mt < 2; mt++)
            #pragma unroll
            for (int nt = 0; nt < 5; nt++) {
                mma16816(o3[mt][nt], a3f[mt][0], w4[nt].x, w4[nt].y);
                mma16816(o3[mt][nt], a3f[mt][1], w4[nt].z, w4[nt].w);
            }
    }

    // ---------------- cross-warp K reduction (2-way over ni) + output -------
    float* sred = (float*)smem;   // aliases A2 region: 64*40 f32 = 10240B
    if (ni == 1) {
        #pragma unroll
        for (int mt = 0; mt < 2; mt++)
            #pragma unroll
            for (int nt = 0; nt < 5; nt++) {
                int j = nt * 8 + 2 * tig;
                int r0 = mi * 32 + mt * 16 + gid;
                int r1 = r0 + 8;
                sred[r0 * 40 + j]     = o3[mt][nt][0];
                sred[r0 * 40 + j + 1] = o3[mt][nt][1];
                sred[r1 * 40 + j]     = o3[mt][nt][2];
                sred[r1 * 40 + j + 1] = o3[mt][nt][3];
            }
    }
    __syncthreads();
    if (ni == 0) {
        #pragma unroll
        for (int mt = 0; mt < 2; mt++)
            #pragma unroll
            for (int nt = 0; nt < 5; nt++) {
                int j = nt * 8 + 2 * tig;
                int r0 = mi * 32 + mt * 16 + gid;
                int r1 = r0 + 8;
                float s0 = o3[mt][nt][0] + sred[r0 * 40 + j]     + b4s[j];
                float s1 = o3[mt][nt][1] + sred[r0 * 40 + j + 1] + b4s[j + 1];
                float s2 = o3[mt][nt][2] + sred[r1 * 40 + j]     + b4s[j];
                float s3 = o3[mt][nt][3] + sred[r1 * 40 + j + 1] + b4s[j + 1];
                *(float2*)(out + ((size_t)blk * RPB + r0) * 40 + j) = make_float2(s0, s1);
                *(float2*)(out + ((size_t)blk * RPB + r1) * 40 + j) = make_float2(s2, s3);
            }
    }
}

extern "C" void kernel_launch(void* const* d_in, const int* in_sizes, int n_in,
                              void* d_out, int out_size) {
    const float* x  = (const float*)d_in[0];
    const float* W1 = (const float*)d_in[1];
    const float* b1 = (const float*)d_in[2];
    const float* W2 = (const float*)d_in[3];
    const float* b2 = (const float*)d_in[4];
    const float* W4 = (const float*)d_in[5];
    const float* b4 = (const float*)d_in[6];
    float* out = (float*)d_out;

    prep_kernel<<<42, 256>>>(W2, W4);

    const int B = in_sizes[0] / 15;      // 131072
    const int grid = B / RPB;            // 2048
    cudaFuncSetAttribute(dqn_hmma_kernel,
                         cudaFuncAttributeMaxDynamicSharedMemorySize, SMEM_BYTES);
    dqn_hmma_kernel<<<grid, TPB, SMEM_BYTES>>>(x, W1, b1, b2, b4, out);
}

// round 13
// speedup vs baseline: 2.1147x; 1.4450x over previous
#include <cuda_runtime.h>
#include <cuda_fp16.h>
#include <cstdint>

#define TPB 128
#define RPB 64
#define PAD 136    // fp16 elems per k-row of A2 tile (272B stride, conflict-free)
#define IPAD 72    // fp16 elems per row of inp tile (144B stride, conflict-free)

// ---------------- fragment-ordered fp16 weights in device globals ----------
// W2: entries (c8 x ni2 x kt8 x ntp2) x 32 lanes; uint4 = {ntA.b0, ntA.b1, ntB.b0, ntB.b1}
__device__ __align__(16) uint4 gW2f[8192];
// W4: entries (c8 x ni2 x nt5) x 32 lanes; uint4 = {kt0.b0, kt0.b1, kt1.b0, kt1.b1}
__device__ __align__(16) uint4 gW4f[2560];
// W1: entries (ni2 x kt3 x ntp4) x 32 lanes; K=48 zero-padded from 36
__device__ __align__(16) uint4 gW1f[768];

__device__ __forceinline__ uint32_t pack_h2(float a, float b) {
    __half2 p = __floats2half2_rn(a, b);
    return *(uint32_t*)&p;
}

__global__ void prep_kernel(const float* __restrict__ W2,
                            const float* __restrict__ W4,
                            const float* __restrict__ W1) {
    int idx = blockIdx.x * blockDim.x + threadIdx.x;
    if (idx < 8192) {
        int lane = idx & 31, fid = idx >> 5;
        int ntp = fid & 1, kt = (fid >> 1) & 7, ni = (fid >> 4) & 1, c = fid >> 5;
        int nA = c * 64 + ni * 32 + (2 * ntp) * 8 + (lane >> 2);
        int nB = nA + 8;
        int k0 = kt * 16 + (lane & 3) * 2;
        uint4 v;
        v.x = pack_h2(W2[k0 * 512 + nA],       W2[(k0 + 1) * 512 + nA]);
        v.y = pack_h2(W2[(k0 + 8) * 512 + nA], W2[(k0 + 9) * 512 + nA]);
        v.z = pack_h2(W2[k0 * 512 + nB],       W2[(k0 + 1) * 512 + nB]);
        v.w = pack_h2(W2[(k0 + 8) * 512 + nB], W2[(k0 + 9) * 512 + nB]);
        gW2f[idx] = v;
    } else if (idx < 10752) {
        int i = idx - 8192;
        int lane = i & 31, fid = i >> 5;
        int nt = fid % 5, r = fid / 5;
        int ni = r & 1, c = r >> 1;
        int n = nt * 8 + (lane >> 2);
        int k0 = c * 64 + ni * 32 + (lane & 3) * 2;
        int k1 = k0 + 16;
        uint4 v;
        v.x = pack_h2(W4[k0 * 40 + n],       W4[(k0 + 1) * 40 + n]);
        v.y = pack_h2(W4[(k0 + 8) * 40 + n], W4[(k0 + 9) * 40 + n]);
        v.z = pack_h2(W4[k1 * 40 + n],       W4[(k1 + 1) * 40 + n]);
        v.w = pack_h2(W4[(k1 + 8) * 40 + n], W4[(k1 + 9) * 40 + n]);
        gW4f[i] = v;
    } else if (idx < 11520) {
        int i = idx - 10752;
        int lane = i & 31, fid = i >> 5;           // fid < 24
        int ntp = fid & 3;
        int kt = (fid >> 2) % 3;
        int ni = fid / 12;
        int nA = ni * 64 + ntp * 16 + (lane >> 2);
        int nB = nA + 8;
        int k0 = kt * 16 + (lane & 3) * 2;
        float a0 = (k0     < 36) ? W1[(k0    ) * 128 + nA] : 0.f;
        float a1 = (k0 + 1 < 36) ? W1[(k0 + 1) * 128 + nA] : 0.f;
        float a2 = (k0 + 8 < 36) ? W1[(k0 + 8) * 128 + nA] : 0.f;
        float a3 = (k0 + 9 < 36) ? W1[(k0 + 9) * 128 + nA] : 0.f;
        float b0 = (k0     < 36) ? W1[(k0    ) * 128 + nB] : 0.f;
        float b1_ = (k0 + 1 < 36) ? W1[(k0 + 1) * 128 + nB] : 0.f;
        float b2_ = (k0 + 8 < 36) ? W1[(k0 + 8) * 128 + nB] : 0.f;
        float b3 = (k0 + 9 < 36) ? W1[(k0 + 9) * 128 + nB] : 0.f;
        uint4 v;
        v.x = pack_h2(a0, a1);
        v.y = pack_h2(a2, a3);
        v.z = pack_h2(b0, b1_);
        v.w = pack_h2(b2_, b3);
        gW1f[i] = v;
    }
}

// ---------------- PTX helpers ----------------
__device__ __forceinline__ uint32_t smem_u32(const void* p) {
    uint32_t a;
    asm("{ .reg .u64 t; cvta.to.shared.u64 t, %1; cvt.u32.u64 %0, t; }"
        : "=r"(a) : "l"(p));
    return a;
}
__device__ __forceinline__ void ldsm_x4(uint32_t* r, uint32_t addr) {
    asm volatile("ldmatrix.sync.aligned.m8n8.x4.shared.b16 {%0,%1,%2,%3}, [%4];"
        : "=r"(r[0]), "=r"(r[1]), "=r"(r[2]), "=r"(r[3]) : "r"(addr));
}
__device__ __forceinline__ void mma16816(float* d, const uint32_t* a,
                                         uint32_t b0, uint32_t b1) {
    asm volatile("mma.sync.aligned.m16n8k16.row.col.f32.f16.f16.f32 "
        "{%0,%1,%2,%3}, {%4,%5,%6,%7}, {%8,%9}, {%0,%1,%2,%3};"
        : "+f"(d[0]), "+f"(d[1]), "+f"(d[2]), "+f"(d[3])
        : "r"(a[0]), "r"(a[1]), "r"(a[2]), "r"(a[3]), "r"(b0), "r"(b1));
}
__device__ __forceinline__ uint32_t pack_relu_h2(float v0, float v1, float b0, float b1) {
    __half2 p = __floats2half2_rn(fmaxf(v0 + b0, 0.f), fmaxf(v1 + b1, 0.f));
    return *(uint32_t*)&p;
}

// ---------------- smem layout (bytes) ----------------
#define S_A2H   0          // h1 hi [64][PAD] f16 = 17408 ; later sred 10240
#define S_INP   17408      // inp tile [64][IPAD] f16 = 9216
#define S_XS    26624      // x staging 960 f32 = 3840
#define S_BIAS  30464      // b1(128) b2(512) b4(40) f32 = 2720
#define SMEM_BYTES 33184

__global__ __launch_bounds__(TPB, 3)
void dqn_hmma_kernel(const float* __restrict__ x,
                     const float* __restrict__ b1,
                     const float* __restrict__ b2,
                     const float* __restrict__ b4,
                     float* __restrict__ out) {
    extern __shared__ char smem[];
    const uint32_t sb = smem_u32(smem);
    const int t    = threadIdx.x;
    const int wid  = t >> 5;
    const int lane = t & 31;
    const int blk  = blockIdx.x;

    float* b1s = (float*)(smem + S_BIAS);
    float* b2s = b1s + 128;
    float* b4s = b2s + 512;
    float* xs  = (float*)(smem + S_XS);

    // ---------------- stage: zero inp tile, x rows, biases ----------------
    {
        uint4 z = make_uint4(0, 0, 0, 0);
        uint4* ztile = (uint4*)(smem + S_INP);
        #pragma unroll
        for (int i = 0; i < 5; i++) {
            int idx = i * TPB + t;
            if (idx < 576) ztile[idx] = z;
        }
        const float* xg = x + (size_t)blk * (RPB * 15);
        #pragma unroll
        for (int i = 0; i < 8; i++) {
            int idx = i * TPB + t;
            if (idx < 960) xs[idx] = xg[idx];
        }
        if (t < 128) b1s[t] = b1[t];
        #pragma unroll
        for (int i = 0; i < 4; i++) b2s[i * TPB + t] = b2[i * TPB + t];
        if (t < 40) b4s[t] = b4[t];
    }
    __syncthreads();

    // ---------------- build inp tile (fp16, one-hots exact) ----------------
    if (t < 64) {
        const float* xr = xs + t * 15;
        float v[48];
        #pragma unroll
        for (int i = 0; i < 48; i++) v[i] = 0.f;
        #pragma unroll
        for (int k = 0; k < 11; k++) v[k] = xr[k];
        int hh = (int)xr[11];      hh = hh < 0 ? 0 : (hh > 3 ? 3 : hh);
        int n0 = (int)xr[12] - 1;  n0 = n0 < 0 ? 0 : (n0 > 6 ? 6 : n0);
        int n1 = (int)xr[13] - 1;  n1 = n1 < 0 ? 0 : (n1 > 6 ? 6 : n1);
        int n2 = (int)xr[14] - 1;  n2 = n2 < 0 ? 0 : (n2 > 6 ? 6 : n2);
        v[11 + hh] = 1.f; v[15 + n0] = 1.f; v[22 + n1] = 1.f; v[29 + n2] = 1.f;
        __half2* row = (__half2*)(smem + S_INP + (uint32_t)t * IPAD * 2u);
        #pragma unroll
        for (int p = 0; p < 24; p++)
            row[p] = __floats2half2_rn(v[2 * p], v[2 * p + 1]);
    }
    __syncthreads();

    // ---------------- fragment lane mappings ----------------
    const int lr  = lane & 15;
    const int lc  = (lane >> 4) << 3;
    const int gid = lane >> 2;
    const int tig = lane & 3;

    const int mi = wid & 1;                 // M32 block (all layers)
    const int ni = wid >> 1;                // N-half / layer3 K-half

    // ---------------- layer 1 via HMMA: inp[64x48] x W1f -> h1 tile --------
    {
        uint32_t a1[2][3][4];
        #pragma unroll
        for (int kt = 0; kt < 3; kt++)
            #pragma unroll
            for (int mt = 0; mt < 2; mt++) {
                uint32_t off = (uint32_t)((mi * 32 + mt * 16 + lr) * IPAD + kt * 16 + lc) * 2u;
                ldsm_x4(a1[mt][kt], sb + S_INP + off);
            }
        float acc1[2][8][4];
        #pragma unroll
        for (int a = 0; a < 2; a++)
            #pragma unroll
            for (int b = 0; b < 8; b++)
                #pragma unroll
                for (int d = 0; d < 4; d++) acc1[a][b][d] = 0.f;

        const uint4* w1b = gW1f + ni * 12 * 32 + lane;
        #pragma unroll
        for (int kt = 0; kt < 3; kt++) {
            uint4 w[4];
            #pragma unroll
            for (int p = 0; p < 4; p++) w[p] = __ldg(w1b + (kt * 4 + p) * 32);
            #pragma unroll
            for (int mt = 0; mt < 2; mt++)
                #pragma unroll
                for (int p = 0; p < 4; p++) {
                    mma16816(acc1[mt][2 * p],     a1[mt][kt], w[p].x, w[p].y);
                    mma16816(acc1[mt][2 * p + 1], a1[mt][kt], w[p].z, w[p].w);
                }
        }
        // epilogue: +b1, relu, fp16 -> A2 tile
        #pragma unroll
        for (int mt = 0; mt < 2; mt++)
            #pragma unroll
            for (int nt = 0; nt < 8; nt++) {
                int j = ni * 64 + nt * 8 + 2 * tig;
                float bj0 = b1s[j], bj1 = b1s[j + 1];
                int row0 = mi * 32 + mt * 16 + gid;
                int row1 = row0 + 8;
                *(uint32_t*)(smem + S_A2H + (uint32_t)(row0 * PAD + j) * 2u) =
                    pack_relu_h2(acc1[mt][nt][0], acc1[mt][nt][1], bj0, bj1);
                *(uint32_t*)(smem + S_A2H + (uint32_t)(row1 * PAD + j) * 2u) =
                    pack_relu_h2(acc1[mt][nt][2], acc1[mt][nt][3], bj0, bj1);
            }
    }
    __syncthreads();

    // ---- preload register-resident A fragments (h1, 32x128 per warp) ----
    uint32_t a2f[2][8][4];
    #pragma unroll
    for (int kt = 0; kt < 8; kt++)
        #pragma unroll
        for (int mt = 0; mt < 2; mt++) {
            uint32_t off = (uint32_t)((mi * 32 + mt * 16 + lr) * PAD + kt * 16 + lc) * 2u;
            ldsm_x4(a2f[mt][kt], sb + S_A2H + off);
        }
    __syncthreads();   // A2 region now reusable as sred

    float o3[2][5][4];
    #pragma unroll
    for (int a = 0; a < 2; a++)
        #pragma unroll
        for (int b = 0; b < 5; b++)
            #pragma unroll
            for (int d = 0; d < 4; d++) o3[a][b][d] = 0.f;

    // ---------------- chunk loop: 8 x 64 j-cols, NO barriers ----------------
    #pragma unroll 1
    for (int c0 = 0; c0 < 8; c0++) {
        const int c = (c0 + blk) & 7;   // decorrelate L2 pressure across CTAs
        float acc[2][4][4];
        #pragma unroll
        for (int a = 0; a < 2; a++)
            #pragma unroll
            for (int b = 0; b < 4; b++)
                #pragma unroll
                for (int d = 0; d < 4; d++) acc[a][b][d] = 0.f;

        const uint4* w2base = gW2f + ((size_t)(c * 2 + ni) << 9) + lane;
        const uint4* w4base = gW4f + (size_t)((c * 2 + ni) * 5) * 32 + lane;

        #pragma unroll
        for (int kt = 0; kt < 8; kt++) {
            uint4 wA = __ldg(w2base + (kt * 2 + 0) * 32);
            uint4 wB = __ldg(w2base + (kt * 2 + 1) * 32);
            #pragma unroll
            for (int mt = 0; mt < 2; mt++) {
                mma16816(acc[mt][0], a2f[mt][kt], wA.x, wA.y);
                mma16816(acc[mt][1], a2f[mt][kt], wA.z, wA.w);
                mma16816(acc[mt][2], a2f[mt][kt], wB.x, wB.y);
                mma16816(acc[mt][3], a2f[mt][kt], wB.z, wB.w);
            }
        }

        uint4 w4[5];
        #pragma unroll
        for (int nt = 0; nt < 5; nt++) w4[nt] = __ldg(w4base + nt * 32);

        uint32_t a3f[2][2][4];
        #pragma unroll
        for (int mt = 0; mt < 2; mt++)
            #pragma unroll
            for (int nt = 0; nt < 4; nt++) {
                int j = c * 64 + ni * 32 + nt * 8 + 2 * tig;
                float bj0 = b2s[j], bj1 = b2s[j + 1];
                uint32_t p01 = pack_relu_h2(acc[mt][nt][0], acc[mt][nt][1], bj0, bj1);
                uint32_t p23 = pack_relu_h2(acc[mt][nt][2], acc[mt][nt][3], bj0, bj1);
                a3f[mt][nt >> 1][(nt & 1) * 2]     = p01;
                a3f[mt][nt >> 1][(nt & 1) * 2 + 1] = p23;
            }

        #pragma unroll
        for (int mt = 0; mt < 2; mt++)
            #pragma unroll
            for (int nt = 0; nt < 5; nt++) {
                mma16816(o3[mt][nt], a3f[mt][0], w4[nt].x, w4[nt].y);
                mma16816(o3[mt][nt], a3f[mt][1], w4[nt].z, w4[nt].w);
            }
    }

    // ---------------- cross-warp K reduction (2-way over ni) + output -------
    float* sred = (float*)smem;   // aliases A2 region: 64*40 f32 = 10240B
    if (ni == 1) {
        #pragma unroll
        for (int mt = 0; mt < 2; mt++)
            #pragma unroll
            for (int nt = 0; nt < 5; nt++) {
                int j = nt * 8 + 2 * tig;
                int r0 = mi * 32 + mt * 16 + gid;
                int r1 = r0 + 8;
                sred[r0 * 40 + j]     = o3[mt][nt][0];
                sred[r0 * 40 + j + 1] = o3[mt][nt][1];
                sred[r1 * 40 + j]     = o3[mt][nt][2];
                sred[r1 * 40 + j + 1] = o3[mt][nt][3];
            }
    }
    __syncthreads();
    if (ni == 0) {
        #pragma unroll
        for (int mt = 0; mt < 2; mt++)
            #pragma unroll
            for (int nt = 0; nt < 5; nt++) {
                int j = nt * 8 + 2 * tig;
                int r0 = mi * 32 + mt * 16 + gid;
                int r1 = r0 + 8;
                float s0 = o3[mt][nt][0] + sred[r0 * 40 + j]     + b4s[j];
                float s1 = o3[mt][nt][1] + sred[r0 * 40 + j + 1] + b4s[j + 1];
                float s2 = o3[mt][nt][2] + sred[r1 * 40 + j]     + b4s[j];
                float s3 = o3[mt][nt][3] + sred[r1 * 40 + j + 1] + b4s[j + 1];
                *(float2*)(out + ((size_t)blk * RPB + r0) * 40 + j) = make_float2(s0, s1);
                *(float2*)(out + ((size_t)blk * RPB + r1) * 40 + j) = make_float2(s2, s3);
            }
    }
}

extern "C" void kernel_launch(void* const* d_in, const int* in_sizes, int n_in,
                              void* d_out, int out_size) {
    const float* x  = (const float*)d_in[0];
    const float* W1 = (const float*)d_in[1];
    const float* b1 = (const float*)d_in[2];
    const float* W2 = (const float*)d_in[3];
    const float* b2 = (const float*)d_in[4];
    const float* W4 = (const float*)d_in[5];
    const float* b4 = (const float*)d_in[6];
    float* out = (float*)d_out;

    prep_kernel<<<45, 256>>>(W2, W4, W1);

    const int B = in_sizes[0] / 15;      // 131072
    const int grid = B / RPB;            // 2048
    cudaFuncSetAttribute(dqn_hmma_kernel,
                         cudaFuncAttributeMaxDynamicSharedMemorySize, SMEM_BYTES);
    dqn_hmma_kernel<<<grid, TPB, SMEM_BYTES>>>(x, b1, b2, b4, out);
}

// round 14
// speedup vs baseline: 2.1434x; 1.0136x over previous
#include <cuda_runtime.h>
#include <cuda_fp16.h>
#include <cstdint>

#define TPB 128
#define RPB 64
#define PAD 136    // fp16 elems per k-row of A2 tile (272B stride, conflict-free)
#define IPAD 72    // fp16 elems per row of inp tile (144B stride, conflict-free)

// ---------------- fragment-ordered fp16 weights in device globals ----------
// W2: entries (c8 x ni2 x kt8 x ntp2) x 32 lanes; uint4 = {ntA.b0, ntA.b1, ntB.b0, ntB.b1}
__device__ __align__(16) uint4 gW2f[8192];
// W4: entries (c8 x ni2 x nt5) x 32 lanes; uint4 = {kt0.b0, kt0.b1, kt1.b0, kt1.b1}
__device__ __align__(16) uint4 gW4f[2560];
// W1: entries (ni2 x kt3 x ntp4) x 32 lanes; K=48 zero-padded from 36
__device__ __align__(16) uint4 gW1f[768];

__device__ __forceinline__ uint32_t pack_h2(float a, float b) {
    __half2 p = __floats2half2_rn(a, b);
    return *(uint32_t*)&p;
}

__global__ void prep_kernel(const float* __restrict__ W2,
                            const float* __restrict__ W4,
                            const float* __restrict__ W1) {
    int idx = blockIdx.x * blockDim.x + threadIdx.x;
    if (idx < 8192) {
        int lane = idx & 31, fid = idx >> 5;
        int ntp = fid & 1, kt = (fid >> 1) & 7, ni = (fid >> 4) & 1, c = fid >> 5;
        int nA = c * 64 + ni * 32 + (2 * ntp) * 8 + (lane >> 2);
        int nB = nA + 8;
        int k0 = kt * 16 + (lane & 3) * 2;
        uint4 v;
        v.x = pack_h2(W2[k0 * 512 + nA],       W2[(k0 + 1) * 512 + nA]);
        v.y = pack_h2(W2[(k0 + 8) * 512 + nA], W2[(k0 + 9) * 512 + nA]);
        v.z = pack_h2(W2[k0 * 512 + nB],       W2[(k0 + 1) * 512 + nB]);
        v.w = pack_h2(W2[(k0 + 8) * 512 + nB], W2[(k0 + 9) * 512 + nB]);
        gW2f[idx] = v;
    } else if (idx < 10752) {
        int i = idx - 8192;
        int lane = i & 31, fid = i >> 5;
        int nt = fid % 5, r = fid / 5;
        int ni = r & 1, c = r >> 1;
        int n = nt * 8 + (lane >> 2);
        int k0 = c * 64 + ni * 32 + (lane & 3) * 2;
        int k1 = k0 + 16;
        uint4 v;
        v.x = pack_h2(W4[k0 * 40 + n],       W4[(k0 + 1) * 40 + n]);
        v.y = pack_h2(W4[(k0 + 8) * 40 + n], W4[(k0 + 9) * 40 + n]);
        v.z = pack_h2(W4[k1 * 40 + n],       W4[(k1 + 1) * 40 + n]);
        v.w = pack_h2(W4[(k1 + 8) * 40 + n], W4[(k1 + 9) * 40 + n]);
        gW4f[i] = v;
    } else if (idx < 11520) {
        int i = idx - 10752;
        int lane = i & 31, fid = i >> 5;           // fid < 24
        int ntp = fid & 3;
        int kt = (fid >> 2) % 3;
        int ni = fid / 12;
        int nA = ni * 64 + ntp * 16 + (lane >> 2);
        int nB = nA + 8;
        int k0 = kt * 16 + (lane & 3) * 2;
        float a0 = (k0     < 36) ? W1[(k0    ) * 128 + nA] : 0.f;
        float a1 = (k0 + 1 < 36) ? W1[(k0 + 1) * 128 + nA] : 0.f;
        float a2 = (k0 + 8 < 36) ? W1[(k0 + 8) * 128 + nA] : 0.f;
        float a3 = (k0 + 9 < 36) ? W1[(k0 + 9) * 128 + nA] : 0.f;
        float b0 = (k0     < 36) ? W1[(k0    ) * 128 + nB] : 0.f;
        float b1_ = (k0 + 1 < 36) ? W1[(k0 + 1) * 128 + nB] : 0.f;
        float b2_ = (k0 + 8 < 36) ? W1[(k0 + 8) * 128 + nB] : 0.f;
        float b3 = (k0 + 9 < 36) ? W1[(k0 + 9) * 128 + nB] : 0.f;
        uint4 v;
        v.x = pack_h2(a0, a1);
        v.y = pack_h2(a2, a3);
        v.z = pack_h2(b0, b1_);
        v.w = pack_h2(b2_, b3);
        gW1f[i] = v;
    }
}

// ---------------- PTX helpers ----------------
__device__ __forceinline__ uint32_t smem_u32(const void* p) {
    uint32_t a;
    asm("{ .reg .u64 t; cvta.to.shared.u64 t, %1; cvt.u32.u64 %0, t; }"
        : "=r"(a) : "l"(p));
    return a;
}
__device__ __forceinline__ void ldsm_x4(uint32_t* r, uint32_t addr) {
    asm volatile("ldmatrix.sync.aligned.m8n8.x4.shared.b16 {%0,%1,%2,%3}, [%4];"
        : "=r"(r[0]), "=r"(r[1]), "=r"(r[2]), "=r"(r[3]) : "r"(addr));
}
__device__ __forceinline__ void mma16816(float* d, const uint32_t* a,
                                         uint32_t b0, uint32_t b1) {
    asm volatile("mma.sync.aligned.m16n8k16.row.col.f32.f16.f16.f32 "
        "{%0,%1,%2,%3}, {%4,%5,%6,%7}, {%8,%9}, {%0,%1,%2,%3};"
        : "+f"(d[0]), "+f"(d[1]), "+f"(d[2]), "+f"(d[3])
        : "r"(a[0]), "r"(a[1]), "r"(a[2]), "r"(a[3]), "r"(b0), "r"(b1));
}
__device__ __forceinline__ uint32_t pack_relu_h2(float v0, float v1, float b0, float b1) {
    __half2 p = __floats2half2_rn(fmaxf(v0 + b0, 0.f), fmaxf(v1 + b1, 0.f));
    return *(uint32_t*)&p;
}

// ---------------- smem layout (bytes) ----------------
#define S_A2H   0          // h1 hi [64][PAD] f16 = 17408 ; later sred 10240
#define S_INP   17408      // inp tile [64][IPAD] f16 = 9216
#define S_XS    26624      // x staging 960 f32 = 3840
#define S_BIAS  30464      // b1(128) b2(512) b4(40) f32 = 2720
#define SMEM_BYTES 33184

__global__ __launch_bounds__(TPB, 3)
void dqn_hmma_kernel(const float* __restrict__ x,
                     const float* __restrict__ b1,
                     const float* __restrict__ b2,
                     const float* __restrict__ b4,
                     float* __restrict__ out) {
    extern __shared__ char smem[];
    const uint32_t sb = smem_u32(smem);
    const int t    = threadIdx.x;
    const int wid  = t >> 5;
    const int lane = t & 31;
    const int blk  = blockIdx.x;

    float* b1s = (float*)(smem + S_BIAS);
    float* b2s = b1s + 128;
    float* b4s = b2s + 512;
    float* xs  = (float*)(smem + S_XS);

    // ---------------- stage: zero inp tile, x rows, biases ----------------
    {
        uint4 z = make_uint4(0, 0, 0, 0);
        uint4* ztile = (uint4*)(smem + S_INP);
        #pragma unroll
        for (int i = 0; i < 5; i++) {
            int idx = i * TPB + t;
            if (idx < 576) ztile[idx] = z;
        }
        const float* xg = x + (size_t)blk * (RPB * 15);
        #pragma unroll
        for (int i = 0; i < 8; i++) {
            int idx = i * TPB + t;
            if (idx < 960) xs[idx] = xg[idx];
        }
        if (t < 128) b1s[t] = b1[t];
        #pragma unroll
        for (int i = 0; i < 4; i++) b2s[i * TPB + t] = b2[i * TPB + t];
        if (t < 40) b4s[t] = b4[t];
    }
    __syncthreads();

    // ---------------- build inp tile (fp16, one-hots exact) ----------------
    if (t < 64) {
        const float* xr = xs + t * 15;
        float v[48];
        #pragma unroll
        for (int i = 0; i < 48; i++) v[i] = 0.f;
        #pragma unroll
        for (int k = 0; k < 11; k++) v[k] = xr[k];
        int hh = (int)xr[11];      hh = hh < 0 ? 0 : (hh > 3 ? 3 : hh);
        int n0 = (int)xr[12] - 1;  n0 = n0 < 0 ? 0 : (n0 > 6 ? 6 : n0);
        int n1 = (int)xr[13] - 1;  n1 = n1 < 0 ? 0 : (n1 > 6 ? 6 : n1);
        int n2 = (int)xr[14] - 1;  n2 = n2 < 0 ? 0 : (n2 > 6 ? 6 : n2);
        v[11 + hh] = 1.f; v[15 + n0] = 1.f; v[22 + n1] = 1.f; v[29 + n2] = 1.f;
        __half2* row = (__half2*)(smem + S_INP + (uint32_t)t * IPAD * 2u);
        #pragma unroll
        for (int p = 0; p < 24; p++)
            row[p] = __floats2half2_rn(v[2 * p], v[2 * p + 1]);
    }
    __syncthreads();

    // ---------------- fragment lane mappings ----------------
    const int lr  = lane & 15;
    const int lc  = (lane >> 4) << 3;
    const int gid = lane >> 2;
    const int tig = lane & 3;

    const int mi = wid & 1;                 // M32 block (all layers)
    const int ni = wid >> 1;                // N-half / layer3 K-half

    // ---------------- layer 1 via HMMA: inp[64x48] x W1f -> h1 tile --------
    {
        uint32_t a1[2][3][4];
        #pragma unroll
        for (int kt = 0; kt < 3; kt++)
            #pragma unroll
            for (int mt = 0; mt < 2; mt++) {
                uint32_t off = (uint32_t)((mi * 32 + mt * 16 + lr) * IPAD + kt * 16 + lc) * 2u;
                ldsm_x4(a1[mt][kt], sb + S_INP + off);
            }
        float acc1[2][8][4];
        #pragma unroll
        for (int a = 0; a < 2; a++)
            #pragma unroll
            for (int b = 0; b < 8; b++)
                #pragma unroll
                for (int d = 0; d < 4; d++) acc1[a][b][d] = 0.f;

        const uint4* w1b = gW1f + ni * 12 * 32 + lane;
        #pragma unroll
        for (int kt = 0; kt < 3; kt++) {
            uint4 w[4];
            #pragma unroll
            for (int p = 0; p < 4; p++) w[p] = __ldg(w1b + (kt * 4 + p) * 32);
            #pragma unroll
            for (int mt = 0; mt < 2; mt++)
                #pragma unroll
                for (int p = 0; p < 4; p++) {
                    mma16816(acc1[mt][2 * p],     a1[mt][kt], w[p].x, w[p].y);
                    mma16816(acc1[mt][2 * p + 1], a1[mt][kt], w[p].z, w[p].w);
                }
        }
        // epilogue: +b1, relu, fp16 -> A2 tile
        #pragma unroll
        for (int mt = 0; mt < 2; mt++)
            #pragma unroll
            for (int nt = 0; nt < 8; nt++) {
                int j = ni * 64 + nt * 8 + 2 * tig;
                float bj0 = b1s[j], bj1 = b1s[j + 1];
                int row0 = mi * 32 + mt * 16 + gid;
                int row1 = row0 + 8;
                *(uint32_t*)(smem + S_A2H + (uint32_t)(row0 * PAD + j) * 2u) =
                    pack_relu_h2(acc1[mt][nt][0], acc1[mt][nt][1], bj0, bj1);
                *(uint32_t*)(smem + S_A2H + (uint32_t)(row1 * PAD + j) * 2u) =
                    pack_relu_h2(acc1[mt][nt][2], acc1[mt][nt][3], bj0, bj1);
            }
    }
    __syncthreads();

    // ---- preload register-resident A fragments (h1, 32x128 per warp) ----
    uint32_t a2f[2][8][4];
    #pragma unroll
    for (int kt = 0; kt < 8; kt++)
        #pragma unroll
        for (int mt = 0; mt < 2; mt++) {
            uint32_t off = (uint32_t)((mi * 32 + mt * 16 + lr) * PAD + kt * 16 + lc) * 2u;
            ldsm_x4(a2f[mt][kt], sb + S_A2H + off);
        }
    __syncthreads();   // A2 region now reusable as sred

    float o3[2][5][4];
    #pragma unroll
    for (int a = 0; a < 2; a++)
        #pragma unroll
        for (int b = 0; b < 5; b++)
            #pragma unroll
            for (int d = 0; d < 4; d++) o3[a][b][d] = 0.f;

    // ---------------- chunk loop: 8 x 64 j-cols, NO barriers ----------------
    // hoisted loop-invariant fragment bases
    const uint4* w2lane = gW2f + ((size_t)ni << 9) + lane;    // + c*1024
    const uint4* w4lane = gW4f + (size_t)(ni * 5) * 32 + lane; // + c*320

    #pragma unroll 2
    for (int c0 = 0; c0 < 8; c0++) {
        const int c = (c0 + blk) & 7;   // decorrelate L2 pressure across CTAs
        const uint4* w2base = w2lane + (size_t)c * 1024;
        const uint4* w4base = w4lane + (size_t)c * 320;

        // ---- layer3 W4 fragments first: independent of layer2, MMA-covered ----
        uint4 w4[5];
        #pragma unroll
        for (int nt = 0; nt < 5; nt++) w4[nt] = __ldg(w4base + nt * 32);

        float acc[2][4][4];
        #pragma unroll
        for (int a = 0; a < 2; a++)
            #pragma unroll
            for (int b = 0; b < 4; b++)
                #pragma unroll
                for (int d = 0; d < 4; d++) acc[a][b][d] = 0.f;

        #pragma unroll
        for (int kt = 0; kt < 8; kt++) {
            uint4 wA = __ldg(w2base + (kt * 2 + 0) * 32);
            uint4 wB = __ldg(w2base + (kt * 2 + 1) * 32);
            #pragma unroll
            for (int mt = 0; mt < 2; mt++) {
                mma16816(acc[mt][0], a2f[mt][kt], wA.x, wA.y);
                mma16816(acc[mt][1], a2f[mt][kt], wA.z, wA.w);
                mma16816(acc[mt][2], a2f[mt][kt], wB.x, wB.y);
                mma16816(acc[mt][3], a2f[mt][kt], wB.z, wB.w);
            }
        }

        // ---- epilogue in registers: D-frag -> A-frag (h2), +b2, relu, cvt ----
        uint32_t a3f[2][2][4];
        #pragma unroll
        for (int mt = 0; mt < 2; mt++)
            #pragma unroll
            for (int nt = 0; nt < 4; nt++) {
                int j = c * 64 + ni * 32 + nt * 8 + 2 * tig;
                float bj0 = b2s[j], bj1 = b2s[j + 1];
                uint32_t p01 = pack_relu_h2(acc[mt][nt][0], acc[mt][nt][1], bj0, bj1);
                uint32_t p23 = pack_relu_h2(acc[mt][nt][2], acc[mt][nt][3], bj0, bj1);
                a3f[mt][nt >> 1][(nt & 1) * 2]     = p01;
                a3f[mt][nt >> 1][(nt & 1) * 2 + 1] = p23;
            }

        // ---- layer3 partial: K = this warp's j-window (ni half), from regs ----
        #pragma unroll
        for (int mt = 0; mt < 2; mt++)
            #pragma unroll
            for (int nt = 0; nt < 5; nt++) {
                mma16816(o3[mt][nt], a3f[mt][0], w4[nt].x, w4[nt].y);
                mma16816(o3[mt][nt], a3f[mt][1], w4[nt].z, w4[nt].w);
            }
    }

    // ---------------- cross-warp K reduction (2-way over ni) + output -------
    float* sred = (float*)smem;   // aliases A2 region: 64*40 f32 = 10240B
    if (ni == 1) {
        #pragma unroll
        for (int mt = 0; mt < 2; mt++)
            #pragma unroll
            for (int nt = 0; nt < 5; nt++) {
                int j = nt * 8 + 2 * tig;
                int r0 = mi * 32 + mt * 16 + gid;
                int r1 = r0 + 8;
                sred[r0 * 40 + j]     = o3[mt][nt][0];
                sred[r0 * 40 + j + 1] = o3[mt][nt][1];
                sred[r1 * 40 + j]     = o3[mt][nt][2];
                sred[r1 * 40 + j + 1] = o3[mt][nt][3];
            }
    }
    __syncthreads();
    if (ni == 0) {
        #pragma unroll
        for (int mt = 0; mt < 2; mt++)
            #pragma unroll
            for (int nt = 0; nt < 5; nt++) {
                int j = nt * 8 + 2 * tig;
                int r0 = mi * 32 + mt * 16 + gid;
                int r1 = r0 + 8;
                float s0 = o3[mt][nt][0] + sred[r0 * 40 + j]     + b4s[j];
                float s1 = o3[mt][nt][1] + sred[r0 * 40 + j + 1] + b4s[j + 1];
                float s2 = o3[mt][nt][2] + sred[r1 * 40 + j]     + b4s[j];
                float s3 = o3[mt][nt][3] + sred[r1 * 40 + j + 1] + b4s[j + 1];
                *(float2*)(out + ((size_t)blk * RPB + r0) * 40 + j) = make_float2(s0, s1);
                *(float2*)(out + ((size_t)blk * RPB + r1) * 40 + j) = make_float2(s2, s3);
            }
    }
}

extern "C" void kernel_launch(void* const* d_in, const int* in_sizes, int n_in,
                              void* d_out, int out_size) {
    const float* x  = (const float*)d_in[0];
    const float* W1 = (const float*)d_in[1];
    const float* b1 = (const float*)d_in[2];
    const float* W2 = (const float*)d_in[3];
    const float* b2 = (const float*)d_in[4];
    const float* W4 = (const float*)d_in[5];
    const float* b4 = (const float*)d_in[6];
    float* out = (float*)d_out;

    prep_kernel<<<45, 256>>>(W2, W4, W1);

    const int B = in_sizes[0] / 15;      // 131072
    const int grid = B / RPB;            // 2048
    cudaFuncSetAttribute(dqn_hmma_kernel,
                         cudaFuncAttributeMaxDynamicSharedMemorySize, SMEM_BYTES);
    dqn_hmma_kernel<<<grid, TPB, SMEM_BYTES>>>(x, b1, b2, b4, out);
}

// round 15
// speedup vs baseline: 2.2131x; 1.0325x over previous
#include <cuda_runtime.h>
#include <cuda_fp16.h>
#include <cstdint>

#define TPB 128
#define RPB 64
#define PAD 136    // fp16 elems per k-row of A2 tile (272B stride, conflict-free)
#define IPAD 72    // fp16 elems per row of inp tile (144B stride, conflict-free)

// ---------------- fragment-ordered fp16 weights in device globals ----------
// W2: entries (c8 x ni2 x kt8 x ntp2) x 32 lanes; uint4 = {ntA.b0, ntA.b1, ntB.b0, ntB.b1}
__device__ __align__(16) uint4 gW2f[8192];
// W4: entries (c8 x ni2 x nt5) x 32 lanes; uint4 = {kt0.b0, kt0.b1, kt1.b0, kt1.b1}
__device__ __align__(16) uint4 gW4f[2560];
// W1: entries (ni2 x kt3 x ntp4) x 32 lanes; K=48 zero-padded from 36
__device__ __align__(16) uint4 gW1f[768];

__device__ __forceinline__ uint32_t pack_h2(float a, float b) {
    __half2 p = __floats2half2_rn(a, b);
    return *(uint32_t*)&p;
}

__global__ void prep_kernel(const float* __restrict__ W2,
                            const float* __restrict__ W4,
                            const float* __restrict__ W1) {
    int idx = blockIdx.x * blockDim.x + threadIdx.x;
    if (idx < 8192) {
        int lane = idx & 31, fid = idx >> 5;
        int ntp = fid & 1, kt = (fid >> 1) & 7, ni = (fid >> 4) & 1, c = fid >> 5;
        int nA = c * 64 + ni * 32 + (2 * ntp) * 8 + (lane >> 2);
        int nB = nA + 8;
        int k0 = kt * 16 + (lane & 3) * 2;
        uint4 v;
        v.x = pack_h2(W2[k0 * 512 + nA],       W2[(k0 + 1) * 512 + nA]);
        v.y = pack_h2(W2[(k0 + 8) * 512 + nA], W2[(k0 + 9) * 512 + nA]);
        v.z = pack_h2(W2[k0 * 512 + nB],       W2[(k0 + 1) * 512 + nB]);
        v.w = pack_h2(W2[(k0 + 8) * 512 + nB], W2[(k0 + 9) * 512 + nB]);
        gW2f[idx] = v;
    } else if (idx < 10752) {
        int i = idx - 8192;
        int lane = i & 31, fid = i >> 5;
        int nt = fid % 5, r = fid / 5;
        int ni = r & 1, c = r >> 1;
        int n = nt * 8 + (lane >> 2);
        int k0 = c * 64 + ni * 32 + (lane & 3) * 2;
        int k1 = k0 + 16;
        uint4 v;
        v.x = pack_h2(W4[k0 * 40 + n],       W4[(k0 + 1) * 40 + n]);
        v.y = pack_h2(W4[(k0 + 8) * 40 + n], W4[(k0 + 9) * 40 + n]);
        v.z = pack_h2(W4[k1 * 40 + n],       W4[(k1 + 1) * 40 + n]);
        v.w = pack_h2(W4[(k1 + 8) * 40 + n], W4[(k1 + 9) * 40 + n]);
        gW4f[i] = v;
    } else if (idx < 11520) {
        int i = idx - 10752;
        int lane = i & 31, fid = i >> 5;           // fid < 24
        int ntp = fid & 3;
        int kt = (fid >> 2) % 3;
        int ni = fid / 12;
        int nA = ni * 64 + ntp * 16 + (lane >> 2);
        int nB = nA + 8;
        int k0 = kt * 16 + (lane & 3) * 2;
        float a0 = (k0     < 36) ? W1[(k0    ) * 128 + nA] : 0.f;
        float a1 = (k0 + 1 < 36) ? W1[(k0 + 1) * 128 + nA] : 0.f;
        float a2 = (k0 + 8 < 36) ? W1[(k0 + 8) * 128 + nA] : 0.f;
        float a3 = (k0 + 9 < 36) ? W1[(k0 + 9) * 128 + nA] : 0.f;
        float b0 = (k0     < 36) ? W1[(k0    ) * 128 + nB] : 0.f;
        float b1_ = (k0 + 1 < 36) ? W1[(k0 + 1) * 128 + nB] : 0.f;
        float b2_ = (k0 + 8 < 36) ? W1[(k0 + 8) * 128 + nB] : 0.f;
        float b3 = (k0 + 9 < 36) ? W1[(k0 + 9) * 128 + nB] : 0.f;
        uint4 v;
        v.x = pack_h2(a0, a1);
        v.y = pack_h2(a2, a3);
        v.z = pack_h2(b0, b1_);
        v.w = pack_h2(b2_, b3);
        gW1f[i] = v;
    }
}

// ---------------- PTX helpers ----------------
__device__ __forceinline__ uint32_t smem_u32(const void* p) {
    uint32_t a;
    asm("{ .reg .u64 t; cvta.to.shared.u64 t, %1; cvt.u32.u64 %0, t; }"
        : "=r"(a) : "l"(p));
    return a;
}
__device__ __forceinline__ void ldsm_x4(uint32_t* r, uint32_t addr) {
    asm volatile("ldmatrix.sync.aligned.m8n8.x4.shared.b16 {%0,%1,%2,%3}, [%4];"
        : "=r"(r[0]), "=r"(r[1]), "=r"(r[2]), "=r"(r[3]) : "r"(addr));
}
__device__ __forceinline__ void mma16816(float* d, const uint32_t* a,
                                         uint32_t b0, uint32_t b1) {
    asm volatile("mma.sync.aligned.m16n8k16.row.col.f32.f16.f16.f32 "
        "{%0,%1,%2,%3}, {%4,%5,%6,%7}, {%8,%9}, {%0,%1,%2,%3};"
        : "+f"(d[0]), "+f"(d[1]), "+f"(d[2]), "+f"(d[3])
        : "r"(a[0]), "r"(a[1]), "r"(a[2]), "r"(a[3]), "r"(b0), "r"(b1));
}
__device__ __forceinline__ uint32_t pack_relu_h2(float v0, float v1, float b0, float b1) {
    __half2 p = __floats2half2_rn(fmaxf(v0 + b0, 0.f), fmaxf(v1 + b1, 0.f));
    return *(uint32_t*)&p;
}

// ---------------- smem layout (bytes) ----------------
#define S_A2H   0          // h1 tile [64][PAD] f16 = 17408 (alive through chunk loop)
#define S_INP   17408      // inp tile [64][IPAD] f16 = 9216 ; later sred 10240 (spans into S_XS)
#define S_XS    26624      // x staging 960 f32 = 3840
#define S_BIAS  30464      // b1(128) b2(512) b4(40) f32 = 2720
#define SMEM_BYTES 33184

__global__ __launch_bounds__(TPB, 4)
void dqn_hmma_kernel(const float* __restrict__ x,
                     const float* __restrict__ b1,
                     const float* __restrict__ b2,
                     const float* __restrict__ b4,
                     float* __restrict__ out) {
    extern __shared__ char smem[];
    const uint32_t sb = smem_u32(smem);
    const int t    = threadIdx.x;
    const int wid  = t >> 5;
    const int lane = t & 31;
    const int blk  = blockIdx.x;

    float* b1s = (float*)(smem + S_BIAS);
    float* b2s = b1s + 128;
    float* b4s = b2s + 512;
    float* xs  = (float*)(smem + S_XS);

    // ---------------- stage: zero inp tile, x rows, biases ----------------
    {
        uint4 z = make_uint4(0, 0, 0, 0);
        uint4* ztile = (uint4*)(smem + S_INP);
        #pragma unroll
        for (int i = 0; i < 5; i++) {
            int idx = i * TPB + t;
            if (idx < 576) ztile[idx] = z;
        }
        const float* xg = x + (size_t)blk * (RPB * 15);
        #pragma unroll
        for (int i = 0; i < 8; i++) {
            int idx = i * TPB + t;
            if (idx < 960) xs[idx] = xg[idx];
        }
        if (t < 128) b1s[t] = b1[t];
        #pragma unroll
        for (int i = 0; i < 4; i++) b2s[i * TPB + t] = b2[i * TPB + t];
        if (t < 40) b4s[t] = b4[t];
    }
    __syncthreads();

    // ---------------- build inp tile (fp16, one-hots exact) ----------------
    if (t < 64) {
        const float* xr = xs + t * 15;
        float v[48];
        #pragma unroll
        for (int i = 0; i < 48; i++) v[i] = 0.f;
        #pragma unroll
        for (int k = 0; k < 11; k++) v[k] = xr[k];
        int hh = (int)xr[11];      hh = hh < 0 ? 0 : (hh > 3 ? 3 : hh);
        int n0 = (int)xr[12] - 1;  n0 = n0 < 0 ? 0 : (n0 > 6 ? 6 : n0);
        int n1 = (int)xr[13] - 1;  n1 = n1 < 0 ? 0 : (n1 > 6 ? 6 : n1);
        int n2 = (int)xr[14] - 1;  n2 = n2 < 0 ? 0 : (n2 > 6 ? 6 : n2);
        v[11 + hh] = 1.f; v[15 + n0] = 1.f; v[22 + n1] = 1.f; v[29 + n2] = 1.f;
        __half2* row = (__half2*)(smem + S_INP + (uint32_t)t * IPAD * 2u);
        #pragma unroll
        for (int p = 0; p < 24; p++)
            row[p] = __floats2half2_rn(v[2 * p], v[2 * p + 1]);
    }
    __syncthreads();

    // ---------------- fragment lane mappings ----------------
    const int lr  = lane & 15;
    const int lc  = (lane >> 4) << 3;
    const int gid = lane >> 2;
    const int tig = lane & 3;

    const int mi = wid & 1;                 // M32 block (all layers)
    const int ni = wid >> 1;                // N-half / layer3 K-half

    // ---------------- layer 1 via HMMA: inp[64x48] x W1f -> h1 tile --------
    {
        uint32_t a1[2][3][4];
        #pragma unroll
        for (int kt = 0; kt < 3; kt++)
            #pragma unroll
            for (int mt = 0; mt < 2; mt++) {
                uint32_t off = (uint32_t)((mi * 32 + mt * 16 + lr) * IPAD + kt * 16 + lc) * 2u;
                ldsm_x4(a1[mt][kt], sb + S_INP + off);
            }
        float acc1[2][8][4];
        #pragma unroll
        for (int a = 0; a < 2; a++)
            #pragma unroll
            for (int b = 0; b < 8; b++)
                #pragma unroll
                for (int d = 0; d < 4; d++) acc1[a][b][d] = 0.f;

        const uint4* w1b = gW1f + ni * 12 * 32 + lane;
        #pragma unroll
        for (int kt = 0; kt < 3; kt++) {
            uint4 w[4];
            #pragma unroll
            for (int p = 0; p < 4; p++) w[p] = __ldg(w1b + (kt * 4 + p) * 32);
            #pragma unroll
            for (int mt = 0; mt < 2; mt++)
                #pragma unroll
                for (int p = 0; p < 4; p++) {
                    mma16816(acc1[mt][2 * p],     a1[mt][kt], w[p].x, w[p].y);
                    mma16816(acc1[mt][2 * p + 1], a1[mt][kt], w[p].z, w[p].w);
                }
        }
        // epilogue: +b1, relu, fp16 -> h1 tile
        #pragma unroll
        for (int mt = 0; mt < 2; mt++)
            #pragma unroll
            for (int nt = 0; nt < 8; nt++) {
                int j = ni * 64 + nt * 8 + 2 * tig;
                float bj0 = b1s[j], bj1 = b1s[j + 1];
                int row0 = mi * 32 + mt * 16 + gid;
                int row1 = row0 + 8;
                *(uint32_t*)(smem + S_A2H + (uint32_t)(row0 * PAD + j) * 2u) =
                    pack_relu_h2(acc1[mt][nt][0], acc1[mt][nt][1], bj0, bj1);
                *(uint32_t*)(smem + S_A2H + (uint32_t)(row1 * PAD + j) * 2u) =
                    pack_relu_h2(acc1[mt][nt][2], acc1[mt][nt][3], bj0, bj1);
            }
    }
    __syncthreads();   // h1 tile complete; also frees INP region for sred

    float o3[2][5][4];
    #pragma unroll
    for (int a = 0; a < 2; a++)
        #pragma unroll
        for (int b = 0; b < 5; b++)
            #pragma unroll
            for (int d = 0; d < 4; d++) o3[a][b][d] = 0.f;

    // A-fragment smem base addresses (loop-invariant)
    const uint32_t abase0 = sb + S_A2H + (uint32_t)((mi * 32 + lr) * PAD + lc) * 2u;
    const uint32_t abase1 = abase0 + (uint32_t)(16 * PAD) * 2u;

    // hoisted weight fragment bases
    const uint4* w2lane = gW2f + ((size_t)ni << 9) + lane;     // + c*1024
    const uint4* w4lane = gW4f + (size_t)(ni * 5) * 32 + lane; // + c*320

    // ---------------- chunk loop: 8 x 64 j-cols, NO barriers ----------------
    #pragma unroll 1
    for (int c0 = 0; c0 < 8; c0++) {
        const int c = (c0 + blk) & 7;   // decorrelate L2 pressure across CTAs
        const uint4* w2base = w2lane + (size_t)c * 1024;
        const uint4* w4base = w4lane + (size_t)c * 320;

        // layer3 W4 fragments first (independent; covered by layer2 MMAs)
        uint4 w4[5];
        #pragma unroll
        for (int nt = 0; nt < 5; nt++) w4[nt] = __ldg(w4base + nt * 32);

        float acc[2][4][4];
        #pragma unroll
        for (int a = 0; a < 2; a++)
            #pragma unroll
            for (int b = 0; b < 4; b++)
                #pragma unroll
                for (int d = 0; d < 4; d++) acc[a][b][d] = 0.f;

        #pragma unroll
        for (int kt = 0; kt < 8; kt++) {
            uint32_t a0[4], a1r[4];
            ldsm_x4(a0,  abase0 + kt * 32);
            ldsm_x4(a1r, abase1 + kt * 32);
            uint4 wA = __ldg(w2base + (kt * 2 + 0) * 32);
            uint4 wB = __ldg(w2base + (kt * 2 + 1) * 32);
            mma16816(acc[0][0], a0,  wA.x, wA.y);
            mma16816(acc[0][1], a0,  wA.z, wA.w);
            mma16816(acc[0][2], a0,  wB.x, wB.y);
            mma16816(acc[0][3], a0,  wB.z, wB.w);
            mma16816(acc[1][0], a1r, wA.x, wA.y);
            mma16816(acc[1][1], a1r, wA.z, wA.w);
            mma16816(acc[1][2], a1r, wB.x, wB.y);
            mma16816(acc[1][3], a1r, wB.z, wB.w);
        }

        // ---- epilogue in registers: D-frag -> A-frag (h2), +b2, relu, cvt ----
        uint32_t a3f[2][2][4];
        #pragma unroll
        for (int mt = 0; mt < 2; mt++)
            #pragma unroll
            for (int nt = 0; nt < 4; nt++) {
                int j = c * 64 + ni * 32 + nt * 8 + 2 * tig;
                float bj0 = b2s[j], bj1 = b2s[j + 1];
                uint32_t p01 = pack_relu_h2(acc[mt][nt][0], acc[mt][nt][1], bj0, bj1);
                uint32_t p23 = pack_relu_h2(acc[mt][nt][2], acc[mt][nt][3], bj0, bj1);
                a3f[mt][nt >> 1][(nt & 1) * 2]     = p01;
                a3f[mt][nt >> 1][(nt & 1) * 2 + 1] = p23;
            }

        // ---- layer3 partial: K = this warp's j-window (ni half), from regs ----
        #pragma unroll
        for (int mt = 0; mt < 2; mt++)
            #pragma unroll
            for (int nt = 0; nt < 5; nt++) {
                mma16816(o3[mt][nt], a3f[mt][0], w4[nt].x, w4[nt].y);
                mma16816(o3[mt][nt], a3f[mt][1], w4[nt].z, w4[nt].w);
            }
    }

    // ---------------- cross-warp K reduction (2-way over ni) + output -------
    float* sred = (float*)(smem + S_INP);   // inp region free: 64*40 f32 = 10240B
    if (ni == 1) {
        #pragma unroll
        for (int mt = 0; mt < 2; mt++)
            #pragma unroll
            for (int nt = 0; nt < 5; nt++) {
                int j = nt * 8 + 2 * tig;
                int r0 = mi * 32 + mt * 16 + gid;
                int r1 = r0 + 8;
                sred[r0 * 40 + j]     = o3[mt][nt][0];
                sred[r0 * 40 + j + 1] = o3[mt][nt][1];
                sred[r1 * 40 + j]     = o3[mt][nt][2];
                sred[r1 * 40 + j + 1] = o3[mt][nt][3];
            }
    }
    __syncthreads();
    if (ni == 0) {
        #pragma unroll
        for (int mt = 0; mt < 2; mt++)
            #pragma unroll
            for (int nt = 0; nt < 5; nt++) {
                int j = nt * 8 + 2 * tig;
                int r0 = mi * 32 + mt * 16 + gid;
                int r1 = r0 + 8;
                float s0 = o3[mt][nt][0] + sred[r0 * 40 + j]     + b4s[j];
                float s1 = o3[mt][nt][1] + sred[r0 * 40 + j + 1] + b4s[j + 1];
                float s2 = o3[mt][nt][2] + sred[r1 * 40 + j]     + b4s[j];
                float s3 = o3[mt][nt][3] + sred[r1 * 40 + j + 1] + b4s[j + 1];
                *(float2*)(out + ((size_t)blk * RPB + r0) * 40 + j) = make_float2(s0, s1);
                *(float2*)(out + ((size_t)blk * RPB + r1) * 40 + j) = make_float2(s2, s3);
            }
    }
}

extern "C" void kernel_launch(void* const* d_in, const int* in_sizes, int n_in,
                              void* d_out, int out_size) {
    const float* x  = (const float*)d_in[0];
    const float* W1 = (const float*)d_in[1];
    const float* b1 = (const float*)d_in[2];
    const float* W2 = (const float*)d_in[3];
    const float* b2 = (const float*)d_in[4];
    const float* W4 = (const float*)d_in[5];
    const float* b4 = (const float*)d_in[6];
    float* out = (float*)d_out;

    prep_kernel<<<45, 256>>>(W2, W4, W1);

    const int B = in_sizes[0] / 15;      // 131072
    const int grid = B / RPB;            // 2048
    cudaFuncSetAttribute(dqn_hmma_kernel,
                         cudaFuncAttributeMaxDynamicSharedMemorySize, SMEM_BYTES);
    dqn_hmma_kernel<<<grid, TPB, SMEM_BYTES>>>(x, b1, b2, b4, out);
}